// round 14
// baseline (speedup 1.0000x reference)
#include <cuda_runtime.h>
#include <cuda_fp16.h>
#include <math.h>
#include <stdint.h>

// Problem constants
#define NTOK 2048
#define HDIM 2048
#define IDIM 1408
#define NEXP 8
#define ISH  2816
#define TOPK 2
#define CAP  5120

// ----------------------------- scratch --------------------------------------
__device__ int   g_cnt[NEXP];
__device__ int   g_cnt2[NEXP];
__device__ int   g_off[NEXP];
__device__ int   g_rows_token[CAP];
__device__ int   g_rows_slot[CAP];
__device__ float g_rows_w[CAP];
__device__ int   g_tki[NTOK * TOPK];
__device__ float g_tkw[NTOK * TOPK];
__device__ __half g_hbuf[(size_t)CAP * IDIM];
__device__ __half g_sbuf[(size_t)NTOK * ISH];
__device__ __half g_partial[(size_t)NTOK * TOPK * HDIM];   // fp16 partials

// fp16 copies of inputs (converted per call)
__device__ __half g_xh [(size_t)NTOK * HDIM];
__device__ __half g_wgh[(size_t)NEXP * HDIM * IDIM];
__device__ __half g_wuh[(size_t)NEXP * HDIM * IDIM];
__device__ __half g_wdh[(size_t)NEXP * IDIM * HDIM];
__device__ __half g_sgh[(size_t)HDIM * ISH];
__device__ __half g_suh[(size_t)HDIM * ISH];
__device__ __half g_sdh[(size_t)ISH * HDIM];

// ----------------------------- helpers --------------------------------------
__device__ __forceinline__ uint32_t smem_u32(const void* p) {
    uint32_t a;
    asm("{ .reg .u64 t; cvta.to.shared.u64 t, %1; cvt.u32.u64 %0, t; }" : "=r"(a) : "l"(p));
    return a;
}
__device__ __forceinline__ uint32_t pk(float x, float y) {
    __half2 h = __floats2half2_rn(x, y);
    return reinterpret_cast<uint32_t&>(h);
}
#define LDSM4(r0, r1, r2, r3, addr) \
    asm volatile("ldmatrix.sync.aligned.m8n8.x4.shared.b16 {%0,%1,%2,%3}, [%4];" \
        : "=r"(r0), "=r"(r1), "=r"(r2), "=r"(r3) : "r"(addr))
#define LDSM4T(r0, r1, r2, r3, addr) \
    asm volatile("ldmatrix.sync.aligned.m8n8.x4.trans.shared.b16 {%0,%1,%2,%3}, [%4];" \
        : "=r"(r0), "=r"(r1), "=r"(r2), "=r"(r3) : "r"(addr))
#define MMA16(c, a, b0, b1) \
    asm volatile("mma.sync.aligned.m16n8k16.row.col.f32.f16.f16.f32 " \
        "{%0,%1,%2,%3},{%4,%5,%6,%7},{%8,%9},{%0,%1,%2,%3};" \
        : "+f"((c)[0]), "+f"((c)[1]), "+f"((c)[2]), "+f"((c)[3]) \
        : "r"((a)[0]), "r"((a)[1]), "r"((a)[2]), "r"((a)[3]), "r"(b0), "r"(b1))
#define CPA16(dst, src) \
    asm volatile("cp.async.cg.shared.global [%0], [%1], 16;" :: "r"(dst), "l"(src))
#define CPCOMMIT() asm volatile("cp.async.commit_group;" ::: "memory")
#define CPWAIT2()  asm volatile("cp.async.wait_group 2;" ::: "memory")

// SMEM layout (bytes). A: 128 rows x 32 halves, pitch 80. B pitches padded.
#define A_PITCH   80
#define A_BYTES   10240
#define BSW_PITCH 144
#define BSW_BYTES 4608
#define BDN_PITCH 272
#define BDN_BYTES 8704
#define STG_SW    (A_BYTES + 2 * BSW_BYTES)   // 19456
#define STG_DN    (A_BYTES + BDN_BYTES)       // 18944
#define NSTG      4
#define SMEM_SW   (NSTG * STG_SW)             // 77824
#define SMEM_DN   (NSTG * STG_DN)             // 75776

// ----------------------------- fp32 -> fp16 converts -------------------------
__device__ __forceinline__ void cvt_loop(const float4* __restrict__ src,
                                         __half* __restrict__ dst, int n16) {
    int stride = gridDim.x * blockDim.x;
    for (int i = blockIdx.x * blockDim.x + threadIdx.x; i < n16; i += stride) {
        float4 v0 = src[4 * i];
        float4 v1 = src[4 * i + 1];
        float4 v2 = src[4 * i + 2];
        float4 v3 = src[4 * i + 3];
        uint4 o0, o1;
        o0.x = pk(v0.x, v0.y); o0.y = pk(v0.z, v0.w);
        o0.z = pk(v1.x, v1.y); o0.w = pk(v1.z, v1.w);
        o1.x = pk(v2.x, v2.y); o1.y = pk(v2.z, v2.w);
        o1.z = pk(v3.x, v3.y); o1.w = pk(v3.z, v3.w);
        *(uint4*)(dst + (size_t)i * 16) = o0;
        *(uint4*)(dst + (size_t)i * 16 + 8) = o1;
    }
}
// shared-swiglu inputs: z = 0..2 -> x, sw_gate, sw_up
__global__ void __launch_bounds__(256) k_cvtX(
    const float4* __restrict__ x,
    const float4* __restrict__ sg, const float4* __restrict__ su) {
    int z = blockIdx.z;
    const float4* src = z == 0 ? x : z == 1 ? sg : su;
    __half* dst = z == 0 ? g_xh : z == 1 ? g_sgh : g_suh;
    int n16 = z == 0 ? NTOK * HDIM / 16 : HDIM * ISH / 16;
    cvt_loop(src, dst, n16);
}
// routed-swiglu weights for a 4-expert half: z = 0..1 -> w_gate, w_up
__global__ void __launch_bounds__(256) k_cvtW(
    const float4* __restrict__ wg, const float4* __restrict__ wu, int e0) {
    constexpr int n16 = 4 * HDIM * IDIM / 16;        // 4 experts per call
    size_t off16 = (size_t)e0 * (HDIM * IDIM / 16);
    int z = blockIdx.z;
    const float4* src = (z == 0 ? wg : wu) + off16 * 4;
    __half* dst = (z == 0 ? g_wgh : g_wuh) + off16 * 16;
    cvt_loop(src, dst, n16);
}
// down-side inputs: z = 0..1 -> w_down, sw_down
__global__ void __launch_bounds__(256) k_cvtB(
    const float4* __restrict__ wd, const float4* __restrict__ sd) {
    int z = blockIdx.z;
    const float4* src = z == 0 ? wd : sd;
    __half* dst = z == 0 ? g_wdh : g_sdh;
    int n16 = z == 0 ? NEXP * IDIM * HDIM / 16 : ISH * HDIM / 16;
    cvt_loop(src, dst, n16);
}

// ----------------------------- small kernels ---------------------------------
__global__ void k_reset() {
    int i = blockIdx.x * blockDim.x + threadIdx.x;
    if (i < NEXP) { g_cnt[i] = 0; g_cnt2[i] = 0; }
    if (i < CAP)  { g_rows_token[i] = 0; g_rows_slot[i] = -1; g_rows_w[i] = 0.f; }
}

__global__ void k_gate(const float* __restrict__ x, const float* __restrict__ gw) {
    int n = blockIdx.x;
    int tid = threadIdx.x;
    const float* xr = x + (size_t)n * HDIM;
    float acc[NEXP];
#pragma unroll
    for (int e = 0; e < NEXP; e++) acc[e] = 0.f;
    for (int h = tid; h < HDIM; h += 128) {
        float xv = xr[h];
#pragma unroll
        for (int e = 0; e < NEXP; e++) acc[e] += xv * gw[e * HDIM + h];
    }
    __shared__ float s[NEXP][128];
#pragma unroll
    for (int e = 0; e < NEXP; e++) s[e][tid] = acc[e];
    __syncthreads();
    for (int st = 64; st > 0; st >>= 1) {
        if (tid < st) {
#pragma unroll
            for (int e = 0; e < NEXP; e++) s[e][tid] += s[e][tid + st];
        }
        __syncthreads();
    }
    if (tid == 0) {
        float l[NEXP];
        float m = -1e30f;
#pragma unroll
        for (int e = 0; e < NEXP; e++) { l[e] = s[e][0]; m = fmaxf(m, l[e]); }
        float d = 0.f;
#pragma unroll
        for (int e = 0; e < NEXP; e++) d += expf(l[e] - m);
        int i1 = 0;
#pragma unroll
        for (int e = 1; e < NEXP; e++) if (l[e] > l[i1]) i1 = e;
        int i2 = -1;
#pragma unroll
        for (int e = 0; e < NEXP; e++) {
            if (e == i1) continue;
            if (i2 < 0 || l[e] > l[i2]) i2 = e;
        }
        g_tki[n * 2 + 0] = i1; g_tkw[n * 2 + 0] = expf(l[i1] - m) / d;
        g_tki[n * 2 + 1] = i2; g_tkw[n * 2 + 1] = expf(l[i2] - m) / d;
        atomicAdd(&g_cnt[i1], 1);
        atomicAdd(&g_cnt[i2], 1);
    }
}

__global__ void k_scanplace() {
    int tid = threadIdx.x;
    if (tid == 0) {
        int o = 0;
        for (int e = 0; e < NEXP; e++) {
            g_off[e] = o;
            o += ((g_cnt[e] + 127) / 128) * 128;
        }
    }
    __syncthreads();
    for (int i = tid; i < NTOK * TOPK; i += blockDim.x) {
        int e = g_tki[i];
        int p = g_off[e] + atomicAdd(&g_cnt2[e], 1);
        g_rows_token[p] = i >> 1;
        g_rows_slot[p]  = i;
        g_rows_w[p]     = g_tkw[i];
    }
}

// ----------------------------- SwiGLU fp16 mma GEMM --------------------------
// ROUTED: grid (16, IDIM/64, 4), expert = ebase + blockIdx.z.
// !ROUTED: grid (16, ISH/64, 1).
// CTA 128M x 64N vs two B matrices. 4-stage cp.async pipeline, k-chunk 32.
template<bool ROUTED>
__global__ void __launch_bounds__(256, 2) k_swiglu_t(int ebase)
{
    constexpr int K = HDIM;
    constexpr int ncols = ROUTED ? IDIM : ISH;
    const int e = ROUTED ? (ebase + blockIdx.z) : 0;
    int cnt, rowbase;
    const __half *B1, *B2;
    __half* C;
    if (ROUTED) {
        cnt = g_cnt[e]; rowbase = g_off[e];
        B1 = g_wgh + (size_t)e * K * IDIM;
        B2 = g_wuh + (size_t)e * K * IDIM;
        C = g_hbuf;
    } else {
        cnt = NTOK; rowbase = 0;
        B1 = g_sgh; B2 = g_suh; C = g_sbuf;
    }
    const int m0 = blockIdx.x * 128;
    if (m0 >= cnt) return;
    const int n0 = blockIdx.y * 64;

    extern __shared__ __align__(16) char sm[];
    const uint32_t sbase = smem_u32(sm);

    const int tid = threadIdx.x;
    const int lane = tid & 31, wid = tid >> 5;
    const int gid = lane >> 2, tig = lane & 3;
    const int wm = wid >> 2, wn = wid & 3;

    // ---- cp.async slots: A = 2 segs/thread, B = 1 seg/thread/matrix ----
    const __half* aseg[2];
    uint32_t aoff[2];
#pragma unroll
    for (int i = 0; i < 2; i++) {
        int idx = i * 256 + tid;
        int m = idx >> 2, q = idx & 3;
        aoff[i] = (uint32_t)(m * A_PITCH + q * 16);
        int tok;
        if (ROUTED) { int gr = m0 + m; tok = (gr < cnt) ? g_rows_token[rowbase + gr] : 0; }
        else tok = m0 + m;
        aseg[i] = g_xh + (size_t)tok * K + q * 8;
    }
    const int bkk = tid >> 3, bslot = tid & 7;
    const uint32_t boff = (uint32_t)(bkk * BSW_PITCH + bslot * 16);
    const __half* b1s = B1 + (size_t)bkk * ncols + n0 + bslot * 8;
    const __half* b2s = B2 + (size_t)bkk * ncols + n0 + bslot * 8;

    float cg[4][2][4], cu[4][2][4];
#pragma unroll
    for (int mt = 0; mt < 4; mt++)
#pragma unroll
        for (int j = 0; j < 2; j++)
#pragma unroll
            for (int c = 0; c < 4; c++) { cg[mt][j][c] = 0.f; cu[mt][j][c] = 0.f; }

    const uint32_t a_l = (uint32_t)((wm * 64 + (lane & 15)) * A_PITCH + (lane >> 4) * 16);
    const uint32_t b_l4 = (uint32_t)((lane & 15) * BSW_PITCH + (lane >> 4) * 16);

    auto ISSUE = [&](int ch, int buf) {
        uint32_t s0 = sbase + buf * STG_SW;
        size_t k0 = (size_t)ch * 32;
        CPA16(s0 + aoff[0], aseg[0] + k0);
        CPA16(s0 + aoff[1], aseg[1] + k0);
        CPA16(s0 + A_BYTES + boff, b1s + k0 * ncols);
        CPA16(s0 + A_BYTES + BSW_BYTES + boff, b2s + k0 * ncols);
    };
    auto COMPUTE = [&](int buf) {
        uint32_t base = sbase + buf * STG_SW;
#pragma unroll
        for (int s = 0; s < 2; s++) {
            uint32_t a[4][4];
#pragma unroll
            for (int mt = 0; mt < 4; mt++)
                LDSM4(a[mt][0], a[mt][1], a[mt][2], a[mt][3],
                      base + a_l + mt * (16 * A_PITCH) + s * 32);
            uint32_t g[4], u[4];
            uint32_t baddr = base + A_BYTES + b_l4 + s * (16 * BSW_PITCH) + wn * 32;
            LDSM4T(g[0], g[1], g[2], g[3], baddr);
            LDSM4T(u[0], u[1], u[2], u[3], baddr + BSW_BYTES);
#pragma unroll
            for (int mt = 0; mt < 4; mt++) {
                MMA16(cg[mt][0], a[mt], g[0], g[1]);
                MMA16(cu[mt][0], a[mt], u[0], u[1]);
                MMA16(cg[mt][1], a[mt], g[2], g[3]);
                MMA16(cu[mt][1], a[mt], u[2], u[3]);
            }
        }
    };

    constexpr int NC = K / 32;
#pragma unroll
    for (int s = 0; s < NSTG - 1; s++) { ISSUE(s, s); CPCOMMIT(); }
    for (int ch = 0; ch < NC; ch++) {
        CPWAIT2();
        __syncthreads();
        int nx = ch + NSTG - 1;
        if (nx < NC) ISSUE(nx, nx % NSTG);
        CPCOMMIT();
        COMPUTE(ch % NSTG);
    }

    // ---- epilogue: silu(gate)*up -> fp16 ----
#pragma unroll
    for (int mt = 0; mt < 4; mt++) {
        int r0 = m0 + wm * 64 + mt * 16 + gid;
        size_t row0 = (size_t)(rowbase + r0);
        size_t row1 = row0 + 8;
#pragma unroll
        for (int j = 0; j < 2; j++) {
            int col = n0 + wn * 16 + j * 8 + 2 * tig;
            float g0 = cg[mt][j][0], g1 = cg[mt][j][1], g2 = cg[mt][j][2], g3 = cg[mt][j][3];
            float o0 = g0 / (1.f + expf(-g0)) * cu[mt][j][0];
            float o1 = g1 / (1.f + expf(-g1)) * cu[mt][j][1];
            float o2 = g2 / (1.f + expf(-g2)) * cu[mt][j][2];
            float o3 = g3 / (1.f + expf(-g3)) * cu[mt][j][3];
            *(uint32_t*)(C + row0 * ncols + col) = pk(o0, o1);
            *(uint32_t*)(C + row1 * ncols + col) = pk(o2, o3);
        }
    }
}

// ----------------------------- fused down-proj fp16 mma GEMM -----------------
// grid (16, 16, NEXP+1): z<8 routed expert z (-> g_partial fp16, weighted scatter),
// z=8 shared expert (-> out, plain store; partials added by k_combine).
// CTA 128M x 128N. 4-stage cp.async pipeline, k-chunk 32.
__global__ void __launch_bounds__(256, 2) k_down_f(float* __restrict__ out)
{
    const int z = blockIdx.z;
    const bool routed = (z < NEXP);
    int cnt, rowbase, K;
    const __half *B, *A;
    if (routed) {
        cnt = g_cnt[z]; rowbase = g_off[z]; K = IDIM;
        B = g_wdh + (size_t)z * IDIM * HDIM;
        A = g_hbuf;
    } else {
        cnt = NTOK; rowbase = 0; K = ISH;
        B = g_sdh;
        A = g_sbuf;
    }
    const int m0 = blockIdx.x * 128;
    if (m0 >= cnt) return;
    const int n0 = blockIdx.y * 128;

    extern __shared__ __align__(16) char sm[];
    const uint32_t sbase = smem_u32(sm);

    const int tid = threadIdx.x;
    const int lane = tid & 31, wid = tid >> 5;
    const int gid = lane >> 2, tig = lane & 3;
    const int wm = wid >> 2, wn = wid & 3;

    // ---- cp.async slots ----
    const __half* aseg[2];
    uint32_t aoff[2];
#pragma unroll
    for (int i = 0; i < 2; i++) {
        int idx = i * 256 + tid;
        int m = idx >> 2, q = idx & 3;
        aoff[i] = (uint32_t)(m * A_PITCH + q * 16);
        aseg[i] = A + (size_t)(rowbase + m0 + m) * K + q * 8;
    }
    const __half* bseg[2];
    uint32_t boff[2];
#pragma unroll
    for (int i = 0; i < 2; i++) {
        int idx = i * 256 + tid;
        int kk = idx >> 4, slot = idx & 15;
        boff[i] = (uint32_t)(kk * BDN_PITCH + slot * 16);
        bseg[i] = B + (size_t)kk * HDIM + n0 + slot * 8;
    }

    float cc[4][4][4];
#pragma unroll
    for (int mt = 0; mt < 4; mt++)
#pragma unroll
        for (int j = 0; j < 4; j++)
#pragma unroll
            for (int c = 0; c < 4; c++) cc[mt][j][c] = 0.f;

    const uint32_t a_l = (uint32_t)((wm * 64 + (lane & 15)) * A_PITCH + (lane >> 4) * 16);
    const uint32_t b_l4 = (uint32_t)((lane & 15) * BDN_PITCH + (lane >> 4) * 16);

    auto ISSUE = [&](int ch, int buf) {
        uint32_t s0 = sbase + buf * STG_DN;
        size_t k0 = (size_t)ch * 32;
        CPA16(s0 + aoff[0], aseg[0] + k0);
        CPA16(s0 + aoff[1], aseg[1] + k0);
        CPA16(s0 + A_BYTES + boff[0], bseg[0] + k0 * HDIM);
        CPA16(s0 + A_BYTES + boff[1], bseg[1] + k0 * HDIM);
    };
    auto COMPUTE = [&](int buf) {
        uint32_t base = sbase + buf * STG_DN;
#pragma unroll
        for (int s = 0; s < 2; s++) {
            uint32_t a[4][4];
#pragma unroll
            for (int mt = 0; mt < 4; mt++)
                LDSM4(a[mt][0], a[mt][1], a[mt][2], a[mt][3],
                      base + a_l + mt * (16 * A_PITCH) + s * 32);
#pragma unroll
            for (int t = 0; t < 2; t++) {
                uint32_t b[4];
                LDSM4T(b[0], b[1], b[2], b[3],
                       base + A_BYTES + b_l4 + s * (16 * BDN_PITCH) + wn * 64 + t * 32);
#pragma unroll
                for (int mt = 0; mt < 4; mt++) {
                    MMA16(cc[mt][t * 2 + 0], a[mt], b[0], b[1]);
                    MMA16(cc[mt][t * 2 + 1], a[mt], b[2], b[3]);
                }
            }
        }
    };

    const int NC = K / 32;
#pragma unroll
    for (int s = 0; s < NSTG - 1; s++) { ISSUE(s, s); CPCOMMIT(); }
    for (int ch = 0; ch < NC; ch++) {
        CPWAIT2();
        __syncthreads();
        int nx = ch + NSTG - 1;
        if (nx < NC) ISSUE(nx, nx % NSTG);
        CPCOMMIT();
        COMPUTE(ch % NSTG);
    }

    // ---- epilogue ----
#pragma unroll
    for (int mt = 0; mt < 4; mt++) {
        int r0 = m0 + wm * 64 + mt * 16 + gid;
        if (routed) {
            int gr0 = rowbase + r0, gr1 = gr0 + 8;
            int s0 = g_rows_slot[gr0], s1 = g_rows_slot[gr1];
            float w0 = g_rows_w[gr0],  w1 = g_rows_w[gr1];
#pragma unroll
            for (int j = 0; j < 4; j++) {
                int col = n0 + wn * 32 + j * 8 + 2 * tig;
                if (s0 >= 0)
                    *(uint32_t*)(g_partial + (size_t)s0 * HDIM + col) =
                        pk(w0 * cc[mt][j][0], w0 * cc[mt][j][1]);
                if (s1 >= 0)
                    *(uint32_t*)(g_partial + (size_t)s1 * HDIM + col) =
                        pk(w1 * cc[mt][j][2], w1 * cc[mt][j][3]);
            }
        } else {
            int r1 = r0 + 8;
#pragma unroll
            for (int j = 0; j < 4; j++) {
                int col = n0 + wn * 32 + j * 8 + 2 * tig;
                *(float2*)(out + (size_t)r0 * HDIM + col) =
                    make_float2(cc[mt][j][0], cc[mt][j][1]);
                *(float2*)(out + (size_t)r1 * HDIM + col) =
                    make_float2(cc[mt][j][2], cc[mt][j][3]);
            }
        }
    }
}

// ----------------------------- final combine ---------------------------------
__global__ void __launch_bounds__(256) k_combine(float* __restrict__ out) {
    size_t base = ((size_t)blockIdx.x * blockDim.x + threadIdx.x) * 4;
    if (base >= (size_t)NTOK * HDIM) return;
    int n = (int)(base >> 11);          // HDIM = 2048
    int h = (int)(base & 2047);
    float4 o = *(float4*)(out + base);
    const __half2* p0 = (const __half2*)(g_partial + (size_t)(2 * n) * HDIM + h);
    const __half2* p1 = (const __half2*)(g_partial + (size_t)(2 * n + 1) * HDIM + h);
    float2 a0 = __half22float2(p0[0]);
    float2 a1 = __half22float2(p0[1]);
    float2 b0 = __half22float2(p1[0]);
    float2 b1 = __half22float2(p1[1]);
    o.x += a0.x + b0.x;
    o.y += a0.y + b0.y;
    o.z += a1.x + b1.x;
    o.w += a1.y + b1.y;
    *(float4*)(out + base) = o;
}

// ----------------------------- launch ----------------------------------------
extern "C" void kernel_launch(void* const* d_in, const int* in_sizes, int n_in,
                              void* d_out, int out_size)
{
    const float* x       = (const float*)d_in[0];
    const float* gate_w  = (const float*)d_in[1];
    const float* w_gate  = (const float*)d_in[2];
    const float* w_up    = (const float*)d_in[3];
    const float* w_down  = (const float*)d_in[4];
    const float* sw_gate = (const float*)d_in[5];
    const float* sw_up   = (const float*)d_in[6];
    const float* sw_down = (const float*)d_in[7];
    float* out = (float*)d_out;

    cudaFuncSetAttribute(k_swiglu_t<true>,
                         cudaFuncAttributeMaxDynamicSharedMemorySize, SMEM_SW);
    cudaFuncSetAttribute(k_swiglu_t<false>,
                         cudaFuncAttributeMaxDynamicSharedMemorySize, SMEM_SW);
    cudaFuncSetAttribute(k_down_f,
                         cudaFuncAttributeMaxDynamicSharedMemorySize, SMEM_DN);

    // DAG (4 streams — proven safe against the allocation guard at R12):
    //   sX: cvt(x, sw_gate, sw_up) ──eX──> sS: shared swiglu ──eSW──┐
    //   sW: cvtW(experts 0-3) ──eW0── cvtW(experts 4-7) ──eW1──┐    │
    //   sB: cvt(w_down, sw_down) ──eB──────────────────────┐   │    │
    //   main: reset, gate, scanplace                       │   │    │
    //         ─(wait eX,eW0)─ routed swiglu 0-3            │   │    │
    //         ─(wait eW1)─ routed swiglu 4-7                │   │    │
    //         ─(wait eSW,eB)─ down(all) ─ combine <─────────┘───┘────┘
    cudaStream_t sX, sW, sB, sS;
    cudaEvent_t eFork, eX, eW0, eW1, eB, eSW;
    cudaStreamCreateWithFlags(&sX, cudaStreamNonBlocking);
    cudaStreamCreateWithFlags(&sW, cudaStreamNonBlocking);
    cudaStreamCreateWithFlags(&sB, cudaStreamNonBlocking);
    cudaStreamCreateWithFlags(&sS, cudaStreamNonBlocking);
    cudaEventCreateWithFlags(&eFork, cudaEventDisableTiming);
    cudaEventCreateWithFlags(&eX, cudaEventDisableTiming);
    cudaEventCreateWithFlags(&eW0, cudaEventDisableTiming);
    cudaEventCreateWithFlags(&eW1, cudaEventDisableTiming);
    cudaEventCreateWithFlags(&eB, cudaEventDisableTiming);
    cudaEventCreateWithFlags(&eSW, cudaEventDisableTiming);

    cudaEventRecord(eFork, 0);
    cudaStreamWaitEvent(sX, eFork, 0);
    cudaStreamWaitEvent(sW, eFork, 0);
    cudaStreamWaitEvent(sB, eFork, 0);

    // small converts feeding the shared swiglu
    k_cvtX<<<dim3(240, 1, 3), 256, 0, sX>>>(
        (const float4*)x, (const float4*)sw_gate, (const float4*)sw_up);
    cudaEventRecord(eX, sX);

    // routed-weight converts, split into expert halves
    k_cvtW<<<dim3(432, 1, 2), 256, 0, sW>>>(
        (const float4*)w_gate, (const float4*)w_up, 0);
    cudaEventRecord(eW0, sW);
    k_cvtW<<<dim3(432, 1, 2), 256, 0, sW>>>(
        (const float4*)w_gate, (const float4*)w_up, 4);
    cudaEventRecord(eW1, sW);

    // down-side converts (overlap both swiglus)
    k_cvtB<<<dim3(432, 1, 2), 256, 0, sB>>>(
        (const float4*)w_down, (const float4*)sw_down);
    cudaEventRecord(eB, sB);

    // shared swiglu: needs only eX
    cudaStreamWaitEvent(sS, eX, 0);
    {
        dim3 grid(NTOK / 128, ISH / 64, 1);
        k_swiglu_t<false><<<grid, 256, SMEM_SW, sS>>>(0);
    }
    cudaEventRecord(eSW, sS);

    // main: routing chain (concurrent with all converts)
    k_reset<<<(CAP + 255) / 256, 256>>>();
    k_gate<<<NTOK, 128>>>(x, gate_w);
    k_scanplace<<<1, 256>>>();

    // routed swiglu 0-3: needs eX + first weight half (+ scanplace, stream order)
    cudaStreamWaitEvent(0, eX, 0);
    cudaStreamWaitEvent(0, eW0, 0);
    {
        dim3 grid(NTOK / 128, IDIM / 64, 4);
        k_swiglu_t<true><<<grid, 256, SMEM_SW>>>(0);
    }
    // routed swiglu 4-7: needs second weight half
    cudaStreamWaitEvent(0, eW1, 0);
    {
        dim3 grid(NTOK / 128, IDIM / 64, 4);
        k_swiglu_t<true><<<grid, 256, SMEM_SW>>>(4);
    }

    // down: needs routed swiglus (stream order) + shared swiglu + down weights
    cudaStreamWaitEvent(0, eSW, 0);
    cudaStreamWaitEvent(0, eB, 0);
    {
        dim3 grid(NTOK / 128, HDIM / 128, NEXP + 1);
        k_down_f<<<grid, 256, SMEM_DN>>>(out);
    }
    // out += partial[n,0] + partial[n,1]
    k_combine<<<(NTOK * HDIM / 4 + 255) / 256, 256>>>(out);

    cudaStreamDestroy(sX);
    cudaStreamDestroy(sW);
    cudaStreamDestroy(sB);
    cudaStreamDestroy(sS);
    cudaEventDestroy(eFork);
    cudaEventDestroy(eX);
    cudaEventDestroy(eW0);
    cudaEventDestroy(eW1);
    cudaEventDestroy(eB);
    cudaEventDestroy(eSW);
}

// round 15
// speedup vs baseline: 1.5587x; 1.5587x over previous
#include <cuda_runtime.h>
#include <cuda_fp16.h>
#include <math.h>
#include <stdint.h>

// Problem constants
#define NTOK 2048
#define HDIM 2048
#define IDIM 1408
#define NEXP 8
#define ISH  2816
#define TOPK 2
#define CAP  5120

// ----------------------------- scratch --------------------------------------
__device__ int   g_cnt[NEXP];
__device__ int   g_cnt2[NEXP];
__device__ int   g_off[NEXP];
__device__ int   g_rows_token[CAP];
__device__ int   g_rows_slot[CAP];
__device__ float g_rows_w[CAP];
__device__ int   g_tki[NTOK * TOPK];
__device__ float g_tkw[NTOK * TOPK];
__device__ __half g_hbuf[(size_t)CAP * IDIM];
__device__ __half g_sbuf[(size_t)NTOK * ISH];
__device__ __half g_partial[(size_t)NTOK * TOPK * HDIM];   // fp16 partials

// fp16 copies of inputs (converted per call)
__device__ __half g_xh [(size_t)NTOK * HDIM];
__device__ __half g_wgh[(size_t)NEXP * HDIM * IDIM];
__device__ __half g_wuh[(size_t)NEXP * HDIM * IDIM];
__device__ __half g_wdh[(size_t)NEXP * IDIM * HDIM];
__device__ __half g_sgh[(size_t)HDIM * ISH];
__device__ __half g_suh[(size_t)HDIM * ISH];
__device__ __half g_sdh[(size_t)ISH * HDIM];

// ----------------------------- helpers --------------------------------------
__device__ __forceinline__ uint32_t smem_u32(const void* p) {
    uint32_t a;
    asm("{ .reg .u64 t; cvta.to.shared.u64 t, %1; cvt.u32.u64 %0, t; }" : "=r"(a) : "l"(p));
    return a;
}
__device__ __forceinline__ uint32_t pk(float x, float y) {
    __half2 h = __floats2half2_rn(x, y);
    return reinterpret_cast<uint32_t&>(h);
}
#define LDSM4(r0, r1, r2, r3, addr) \
    asm volatile("ldmatrix.sync.aligned.m8n8.x4.shared.b16 {%0,%1,%2,%3}, [%4];" \
        : "=r"(r0), "=r"(r1), "=r"(r2), "=r"(r3) : "r"(addr))
#define LDSM4T(r0, r1, r2, r3, addr) \
    asm volatile("ldmatrix.sync.aligned.m8n8.x4.trans.shared.b16 {%0,%1,%2,%3}, [%4];" \
        : "=r"(r0), "=r"(r1), "=r"(r2), "=r"(r3) : "r"(addr))
#define MMA16(c, a, b0, b1) \
    asm volatile("mma.sync.aligned.m16n8k16.row.col.f32.f16.f16.f32 " \
        "{%0,%1,%2,%3},{%4,%5,%6,%7},{%8,%9},{%0,%1,%2,%3};" \
        : "+f"((c)[0]), "+f"((c)[1]), "+f"((c)[2]), "+f"((c)[3]) \
        : "r"((a)[0]), "r"((a)[1]), "r"((a)[2]), "r"((a)[3]), "r"(b0), "r"(b1))
#define CPA16(dst, src) \
    asm volatile("cp.async.cg.shared.global [%0], [%1], 16;" :: "r"(dst), "l"(src))
#define CPCOMMIT() asm volatile("cp.async.commit_group;" ::: "memory")
#define CPWAIT2()  asm volatile("cp.async.wait_group 2;" ::: "memory")

// SMEM layout (bytes). A: 128 rows x 32 halves, pitch 80. B pitches padded.
#define A_PITCH   80
#define A_BYTES   10240
#define BSW_PITCH 144
#define BSW_BYTES 4608
#define BDN_PITCH 272
#define BDN_BYTES 8704
#define STG_SW    (A_BYTES + 2 * BSW_BYTES)   // 19456
#define STG_DN    (A_BYTES + BDN_BYTES)       // 18944
#define NSTG      4
#define SMEM_SW   (NSTG * STG_SW)             // 77824
#define SMEM_DN   (NSTG * STG_DN)             // 75776

// ----------------------------- fp32 -> fp16 converts -------------------------
__device__ __forceinline__ void cvt_loop(const float4* __restrict__ src,
                                         __half* __restrict__ dst, int n16) {
    int stride = gridDim.x * blockDim.x;
    for (int i = blockIdx.x * blockDim.x + threadIdx.x; i < n16; i += stride) {
        float4 v0 = src[4 * i];
        float4 v1 = src[4 * i + 1];
        float4 v2 = src[4 * i + 2];
        float4 v3 = src[4 * i + 3];
        uint4 o0, o1;
        o0.x = pk(v0.x, v0.y); o0.y = pk(v0.z, v0.w);
        o0.z = pk(v1.x, v1.y); o0.w = pk(v1.z, v1.w);
        o1.x = pk(v2.x, v2.y); o1.y = pk(v2.z, v2.w);
        o1.z = pk(v3.x, v3.y); o1.w = pk(v3.z, v3.w);
        *(uint4*)(dst + (size_t)i * 16) = o0;
        *(uint4*)(dst + (size_t)i * 16 + 8) = o1;
    }
}
// shared-swiglu inputs: z = 0..2 -> x, sw_gate, sw_up
__global__ void __launch_bounds__(256) k_cvtX(
    const float4* __restrict__ x,
    const float4* __restrict__ sg, const float4* __restrict__ su) {
    int z = blockIdx.z;
    const float4* src = z == 0 ? x : z == 1 ? sg : su;
    __half* dst = z == 0 ? g_xh : z == 1 ? g_sgh : g_suh;
    int n16 = z == 0 ? NTOK * HDIM / 16 : HDIM * ISH / 16;
    cvt_loop(src, dst, n16);
}
// routed-swiglu weights: z = 0..1 -> w_gate, w_up
__global__ void __launch_bounds__(256) k_cvtW(
    const float4* __restrict__ wg, const float4* __restrict__ wu) {
    constexpr int n16 = NEXP * HDIM * IDIM / 16;
    int z = blockIdx.z;
    cvt_loop(z == 0 ? wg : wu, z == 0 ? g_wgh : g_wuh, n16);
}
// down-side inputs: z = 0..1 -> w_down, sw_down
__global__ void __launch_bounds__(256) k_cvtB(
    const float4* __restrict__ wd, const float4* __restrict__ sd) {
    int z = blockIdx.z;
    const float4* src = z == 0 ? wd : sd;
    __half* dst = z == 0 ? g_wdh : g_sdh;
    int n16 = z == 0 ? NEXP * IDIM * HDIM / 16 : ISH * HDIM / 16;
    cvt_loop(src, dst, n16);
}

// ----------------------------- small kernels ---------------------------------
__global__ void k_reset() {
    int i = blockIdx.x * blockDim.x + threadIdx.x;
    if (i < NEXP) { g_cnt[i] = 0; g_cnt2[i] = 0; }
    if (i < CAP)  { g_rows_token[i] = 0; g_rows_slot[i] = -1; g_rows_w[i] = 0.f; }
}

__global__ void k_gate(const float* __restrict__ x, const float* __restrict__ gw) {
    int n = blockIdx.x;
    int tid = threadIdx.x;
    const float* xr = x + (size_t)n * HDIM;
    float acc[NEXP];
#pragma unroll
    for (int e = 0; e < NEXP; e++) acc[e] = 0.f;
    for (int h = tid; h < HDIM; h += 128) {
        float xv = xr[h];
#pragma unroll
        for (int e = 0; e < NEXP; e++) acc[e] += xv * gw[e * HDIM + h];
    }
    __shared__ float s[NEXP][128];
#pragma unroll
    for (int e = 0; e < NEXP; e++) s[e][tid] = acc[e];
    __syncthreads();
    for (int st = 64; st > 0; st >>= 1) {
        if (tid < st) {
#pragma unroll
            for (int e = 0; e < NEXP; e++) s[e][tid] += s[e][tid + st];
        }
        __syncthreads();
    }
    if (tid == 0) {
        float l[NEXP];
        float m = -1e30f;
#pragma unroll
        for (int e = 0; e < NEXP; e++) { l[e] = s[e][0]; m = fmaxf(m, l[e]); }
        float d = 0.f;
#pragma unroll
        for (int e = 0; e < NEXP; e++) d += expf(l[e] - m);
        int i1 = 0;
#pragma unroll
        for (int e = 1; e < NEXP; e++) if (l[e] > l[i1]) i1 = e;
        int i2 = -1;
#pragma unroll
        for (int e = 0; e < NEXP; e++) {
            if (e == i1) continue;
            if (i2 < 0 || l[e] > l[i2]) i2 = e;
        }
        g_tki[n * 2 + 0] = i1; g_tkw[n * 2 + 0] = expf(l[i1] - m) / d;
        g_tki[n * 2 + 1] = i2; g_tkw[n * 2 + 1] = expf(l[i2] - m) / d;
        atomicAdd(&g_cnt[i1], 1);
        atomicAdd(&g_cnt[i2], 1);
    }
}

__global__ void k_scanplace() {
    int tid = threadIdx.x;
    if (tid == 0) {
        int o = 0;
        for (int e = 0; e < NEXP; e++) {
            g_off[e] = o;
            o += ((g_cnt[e] + 127) / 128) * 128;
        }
    }
    __syncthreads();
    for (int i = tid; i < NTOK * TOPK; i += blockDim.x) {
        int e = g_tki[i];
        int p = g_off[e] + atomicAdd(&g_cnt2[e], 1);
        g_rows_token[p] = i >> 1;
        g_rows_slot[p]  = i;
        g_rows_w[p]     = g_tkw[i];
    }
}

// ----------------------------- SwiGLU fp16 mma GEMM --------------------------
// ROUTED: grid (16, IDIM/64, NEXP) -> g_hbuf. !ROUTED: grid (16, ISH/64, 1) -> g_sbuf.
// CTA 128M x 64N vs two B matrices. 4-stage cp.async pipeline, k-chunk 32.
template<bool ROUTED>
__global__ void __launch_bounds__(256, 2) k_swiglu_t()
{
    constexpr int K = HDIM;
    constexpr int ncols = ROUTED ? IDIM : ISH;
    const int z = ROUTED ? blockIdx.z : 0;
    int cnt, rowbase;
    const __half *B1, *B2;
    __half* C;
    if (ROUTED) {
        cnt = g_cnt[z]; rowbase = g_off[z];
        B1 = g_wgh + (size_t)z * K * IDIM;
        B2 = g_wuh + (size_t)z * K * IDIM;
        C = g_hbuf;
    } else {
        cnt = NTOK; rowbase = 0;
        B1 = g_sgh; B2 = g_suh; C = g_sbuf;
    }
    const int m0 = blockIdx.x * 128;
    if (m0 >= cnt) return;
    const int n0 = blockIdx.y * 64;

    extern __shared__ __align__(16) char sm[];
    const uint32_t sbase = smem_u32(sm);

    const int tid = threadIdx.x;
    const int lane = tid & 31, wid = tid >> 5;
    const int gid = lane >> 2, tig = lane & 3;
    const int wm = wid >> 2, wn = wid & 3;

    // ---- cp.async slots: A = 2 segs/thread, B = 1 seg/thread/matrix ----
    const __half* aseg[2];
    uint32_t aoff[2];
#pragma unroll
    for (int i = 0; i < 2; i++) {
        int idx = i * 256 + tid;
        int m = idx >> 2, q = idx & 3;
        aoff[i] = (uint32_t)(m * A_PITCH + q * 16);
        int tok;
        if (ROUTED) { int gr = m0 + m; tok = (gr < cnt) ? g_rows_token[rowbase + gr] : 0; }
        else tok = m0 + m;
        aseg[i] = g_xh + (size_t)tok * K + q * 8;
    }
    const int bkk = tid >> 3, bslot = tid & 7;
    const uint32_t boff = (uint32_t)(bkk * BSW_PITCH + bslot * 16);
    const __half* b1s = B1 + (size_t)bkk * ncols + n0 + bslot * 8;
    const __half* b2s = B2 + (size_t)bkk * ncols + n0 + bslot * 8;

    float cg[4][2][4], cu[4][2][4];
#pragma unroll
    for (int mt = 0; mt < 4; mt++)
#pragma unroll
        for (int j = 0; j < 2; j++)
#pragma unroll
            for (int c = 0; c < 4; c++) { cg[mt][j][c] = 0.f; cu[mt][j][c] = 0.f; }

    const uint32_t a_l = (uint32_t)((wm * 64 + (lane & 15)) * A_PITCH + (lane >> 4) * 16);
    const uint32_t b_l4 = (uint32_t)((lane & 15) * BSW_PITCH + (lane >> 4) * 16);

    auto ISSUE = [&](int ch, int buf) {
        uint32_t s0 = sbase + buf * STG_SW;
        size_t k0 = (size_t)ch * 32;
        CPA16(s0 + aoff[0], aseg[0] + k0);
        CPA16(s0 + aoff[1], aseg[1] + k0);
        CPA16(s0 + A_BYTES + boff, b1s + k0 * ncols);
        CPA16(s0 + A_BYTES + BSW_BYTES + boff, b2s + k0 * ncols);
    };
    auto COMPUTE = [&](int buf) {
        uint32_t base = sbase + buf * STG_SW;
#pragma unroll
        for (int s = 0; s < 2; s++) {
            uint32_t a[4][4];
#pragma unroll
            for (int mt = 0; mt < 4; mt++)
                LDSM4(a[mt][0], a[mt][1], a[mt][2], a[mt][3],
                      base + a_l + mt * (16 * A_PITCH) + s * 32);
            uint32_t g[4], u[4];
            uint32_t baddr = base + A_BYTES + b_l4 + s * (16 * BSW_PITCH) + wn * 32;
            LDSM4T(g[0], g[1], g[2], g[3], baddr);
            LDSM4T(u[0], u[1], u[2], u[3], baddr + BSW_BYTES);
#pragma unroll
            for (int mt = 0; mt < 4; mt++) {
                MMA16(cg[mt][0], a[mt], g[0], g[1]);
                MMA16(cu[mt][0], a[mt], u[0], u[1]);
                MMA16(cg[mt][1], a[mt], g[2], g[3]);
                MMA16(cu[mt][1], a[mt], u[2], u[3]);
            }
        }
    };

    constexpr int NC = K / 32;
#pragma unroll
    for (int s = 0; s < NSTG - 1; s++) { ISSUE(s, s); CPCOMMIT(); }
    for (int ch = 0; ch < NC; ch++) {
        CPWAIT2();
        __syncthreads();
        int nx = ch + NSTG - 1;
        if (nx < NC) ISSUE(nx, nx % NSTG);
        CPCOMMIT();
        COMPUTE(ch % NSTG);
    }

    // ---- epilogue: silu(gate)*up -> fp16 ----
#pragma unroll
    for (int mt = 0; mt < 4; mt++) {
        int r0 = m0 + wm * 64 + mt * 16 + gid;
        size_t row0 = (size_t)(rowbase + r0);
        size_t row1 = row0 + 8;
#pragma unroll
        for (int j = 0; j < 2; j++) {
            int col = n0 + wn * 16 + j * 8 + 2 * tig;
            float g0 = cg[mt][j][0], g1 = cg[mt][j][1], g2 = cg[mt][j][2], g3 = cg[mt][j][3];
            float o0 = g0 / (1.f + expf(-g0)) * cu[mt][j][0];
            float o1 = g1 / (1.f + expf(-g1)) * cu[mt][j][1];
            float o2 = g2 / (1.f + expf(-g2)) * cu[mt][j][2];
            float o3 = g3 / (1.f + expf(-g3)) * cu[mt][j][3];
            *(uint32_t*)(C + row0 * ncols + col) = pk(o0, o1);
            *(uint32_t*)(C + row1 * ncols + col) = pk(o2, o3);
        }
    }
}

// ----------------------------- fused down-proj fp16 mma GEMM -----------------
// grid (16, 16, NEXP+1): z<8 routed expert z (-> g_partial fp16, weighted scatter),
// z=8 shared expert (-> out, plain store; partials added by k_combine).
// CTA 128M x 128N. 4-stage cp.async pipeline, k-chunk 32.
__global__ void __launch_bounds__(256, 2) k_down_f(float* __restrict__ out)
{
    const int z = blockIdx.z;
    const bool routed = (z < NEXP);
    int cnt, rowbase, K;
    const __half *B, *A;
    if (routed) {
        cnt = g_cnt[z]; rowbase = g_off[z]; K = IDIM;
        B = g_wdh + (size_t)z * IDIM * HDIM;
        A = g_hbuf;
    } else {
        cnt = NTOK; rowbase = 0; K = ISH;
        B = g_sdh;
        A = g_sbuf;
    }
    const int m0 = blockIdx.x * 128;
    if (m0 >= cnt) return;
    const int n0 = blockIdx.y * 128;

    extern __shared__ __align__(16) char sm[];
    const uint32_t sbase = smem_u32(sm);

    const int tid = threadIdx.x;
    const int lane = tid & 31, wid = tid >> 5;
    const int gid = lane >> 2, tig = lane & 3;
    const int wm = wid >> 2, wn = wid & 3;

    // ---- cp.async slots ----
    const __half* aseg[2];
    uint32_t aoff[2];
#pragma unroll
    for (int i = 0; i < 2; i++) {
        int idx = i * 256 + tid;
        int m = idx >> 2, q = idx & 3;
        aoff[i] = (uint32_t)(m * A_PITCH + q * 16);
        aseg[i] = A + (size_t)(rowbase + m0 + m) * K + q * 8;
    }
    const __half* bseg[2];
    uint32_t boff[2];
#pragma unroll
    for (int i = 0; i < 2; i++) {
        int idx = i * 256 + tid;
        int kk = idx >> 4, slot = idx & 15;
        boff[i] = (uint32_t)(kk * BDN_PITCH + slot * 16);
        bseg[i] = B + (size_t)kk * HDIM + n0 + slot * 8;
    }

    float cc[4][4][4];
#pragma unroll
    for (int mt = 0; mt < 4; mt++)
#pragma unroll
        for (int j = 0; j < 4; j++)
#pragma unroll
            for (int c = 0; c < 4; c++) cc[mt][j][c] = 0.f;

    const uint32_t a_l = (uint32_t)((wm * 64 + (lane & 15)) * A_PITCH + (lane >> 4) * 16);
    const uint32_t b_l4 = (uint32_t)((lane & 15) * BDN_PITCH + (lane >> 4) * 16);

    auto ISSUE = [&](int ch, int buf) {
        uint32_t s0 = sbase + buf * STG_DN;
        size_t k0 = (size_t)ch * 32;
        CPA16(s0 + aoff[0], aseg[0] + k0);
        CPA16(s0 + aoff[1], aseg[1] + k0);
        CPA16(s0 + A_BYTES + boff[0], bseg[0] + k0 * HDIM);
        CPA16(s0 + A_BYTES + boff[1], bseg[1] + k0 * HDIM);
    };
    auto COMPUTE = [&](int buf) {
        uint32_t base = sbase + buf * STG_DN;
#pragma unroll
        for (int s = 0; s < 2; s++) {
            uint32_t a[4][4];
#pragma unroll
            for (int mt = 0; mt < 4; mt++)
                LDSM4(a[mt][0], a[mt][1], a[mt][2], a[mt][3],
                      base + a_l + mt * (16 * A_PITCH) + s * 32);
#pragma unroll
            for (int t = 0; t < 2; t++) {
                uint32_t b[4];
                LDSM4T(b[0], b[1], b[2], b[3],
                       base + A_BYTES + b_l4 + s * (16 * BDN_PITCH) + wn * 64 + t * 32);
#pragma unroll
                for (int mt = 0; mt < 4; mt++) {
                    MMA16(cc[mt][t * 2 + 0], a[mt], b[0], b[1]);
                    MMA16(cc[mt][t * 2 + 1], a[mt], b[2], b[3]);
                }
            }
        }
    };

    const int NC = K / 32;
#pragma unroll
    for (int s = 0; s < NSTG - 1; s++) { ISSUE(s, s); CPCOMMIT(); }
    for (int ch = 0; ch < NC; ch++) {
        CPWAIT2();
        __syncthreads();
        int nx = ch + NSTG - 1;
        if (nx < NC) ISSUE(nx, nx % NSTG);
        CPCOMMIT();
        COMPUTE(ch % NSTG);
    }

    // ---- epilogue ----
#pragma unroll
    for (int mt = 0; mt < 4; mt++) {
        int r0 = m0 + wm * 64 + mt * 16 + gid;
        if (routed) {
            int gr0 = rowbase + r0, gr1 = gr0 + 8;
            int s0 = g_rows_slot[gr0], s1 = g_rows_slot[gr1];
            float w0 = g_rows_w[gr0],  w1 = g_rows_w[gr1];
#pragma unroll
            for (int j = 0; j < 4; j++) {
                int col = n0 + wn * 32 + j * 8 + 2 * tig;
                if (s0 >= 0)
                    *(uint32_t*)(g_partial + (size_t)s0 * HDIM + col) =
                        pk(w0 * cc[mt][j][0], w0 * cc[mt][j][1]);
                if (s1 >= 0)
                    *(uint32_t*)(g_partial + (size_t)s1 * HDIM + col) =
                        pk(w1 * cc[mt][j][2], w1 * cc[mt][j][3]);
            }
        } else {
            int r1 = r0 + 8;
#pragma unroll
            for (int j = 0; j < 4; j++) {
                int col = n0 + wn * 32 + j * 8 + 2 * tig;
                *(float2*)(out + (size_t)r0 * HDIM + col) =
                    make_float2(cc[mt][j][0], cc[mt][j][1]);
                *(float2*)(out + (size_t)r1 * HDIM + col) =
                    make_float2(cc[mt][j][2], cc[mt][j][3]);
            }
        }
    }
}

// ----------------------------- final combine ---------------------------------
__global__ void __launch_bounds__(256) k_combine(float* __restrict__ out) {
    size_t base = ((size_t)blockIdx.x * blockDim.x + threadIdx.x) * 4;
    if (base >= (size_t)NTOK * HDIM) return;
    int n = (int)(base >> 11);          // HDIM = 2048
    int h = (int)(base & 2047);
    float4 o = *(float4*)(out + base);
    const __half2* p0 = (const __half2*)(g_partial + (size_t)(2 * n) * HDIM + h);
    const __half2* p1 = (const __half2*)(g_partial + (size_t)(2 * n + 1) * HDIM + h);
    float2 a0 = __half22float2(p0[0]);
    float2 a1 = __half22float2(p0[1]);
    float2 b0 = __half22float2(p1[0]);
    float2 b1 = __half22float2(p1[1]);
    o.x += a0.x + b0.x;
    o.y += a0.y + b0.y;
    o.z += a1.x + b1.x;
    o.w += a1.y + b1.y;
    *(float4*)(out + base) = o;
}

// ----------------------------- launch ----------------------------------------
extern "C" void kernel_launch(void* const* d_in, const int* in_sizes, int n_in,
                              void* d_out, int out_size)
{
    const float* x       = (const float*)d_in[0];
    const float* gate_w  = (const float*)d_in[1];
    const float* w_gate  = (const float*)d_in[2];
    const float* w_up    = (const float*)d_in[3];
    const float* w_down  = (const float*)d_in[4];
    const float* sw_gate = (const float*)d_in[5];
    const float* sw_up   = (const float*)d_in[6];
    const float* sw_down = (const float*)d_in[7];
    float* out = (float*)d_out;

    cudaFuncSetAttribute(k_swiglu_t<true>,
                         cudaFuncAttributeMaxDynamicSharedMemorySize, SMEM_SW);
    cudaFuncSetAttribute(k_swiglu_t<false>,
                         cudaFuncAttributeMaxDynamicSharedMemorySize, SMEM_SW);
    cudaFuncSetAttribute(k_down_f,
                         cudaFuncAttributeMaxDynamicSharedMemorySize, SMEM_DN);

    // DAG identical to R12 (best passing: 520.8us); convert streams get
    // elevated priority so they win SM slots when co-running with GEMMs.
    //   sX: cvt(x, sw_gate, sw_up) ──eX──> sS: shared swiglu ──eSW──┐
    //   sW: cvt(w_gate, w_up) ──eW──┐                               │
    //   sB: cvt(w_down, sw_down) ──eB────────────────────────────┐  │
    //   main: reset, gate, scanplace ──(wait eX,eW)── routed swiglu  │
    //         ──(wait eSW, eB)── down ── combine <────────────────┘──┘
    int prLo, prHi;   // prHi = greatest priority (numerically lowest)
    cudaDeviceGetStreamPriorityRange(&prLo, &prHi);
    cudaStream_t sX, sW, sB, sS;
    cudaEvent_t eFork, eX, eW, eB, eSW;
    cudaStreamCreateWithPriority(&sX, cudaStreamNonBlocking, prHi);
    cudaStreamCreateWithPriority(&sW, cudaStreamNonBlocking, prHi);
    cudaStreamCreateWithFlags(&sB, cudaStreamNonBlocking);
    cudaStreamCreateWithFlags(&sS, cudaStreamNonBlocking);
    cudaEventCreateWithFlags(&eFork, cudaEventDisableTiming);
    cudaEventCreateWithFlags(&eX, cudaEventDisableTiming);
    cudaEventCreateWithFlags(&eW, cudaEventDisableTiming);
    cudaEventCreateWithFlags(&eB, cudaEventDisableTiming);
    cudaEventCreateWithFlags(&eSW, cudaEventDisableTiming);

    cudaEventRecord(eFork, 0);
    cudaStreamWaitEvent(sX, eFork, 0);
    cudaStreamWaitEvent(sW, eFork, 0);
    cudaStreamWaitEvent(sB, eFork, 0);

    // small converts feeding the shared swiglu
    k_cvtX<<<dim3(240, 1, 3), 256, 0, sX>>>(
        (const float4*)x, (const float4*)sw_gate, (const float4*)sw_up);
    cudaEventRecord(eX, sX);

    // big routed-weight converts (overlap the shared swiglu)
    k_cvtW<<<dim3(432, 1, 2), 256, 0, sW>>>(
        (const float4*)w_gate, (const float4*)w_up);
    cudaEventRecord(eW, sW);

    // down-side converts (overlap both swiglus)
    k_cvtB<<<dim3(432, 1, 2), 256, 0, sB>>>(
        (const float4*)w_down, (const float4*)sw_down);
    cudaEventRecord(eB, sB);

    // shared swiglu: needs only eX
    cudaStreamWaitEvent(sS, eX, 0);
    {
        dim3 grid(NTOK / 128, ISH / 64, 1);
        k_swiglu_t<false><<<grid, 256, SMEM_SW, sS>>>();
    }
    cudaEventRecord(eSW, sS);

    // main: routing chain (concurrent with all converts)
    k_reset<<<(CAP + 255) / 256, 256>>>();
    k_gate<<<NTOK, 128>>>(x, gate_w);
    k_scanplace<<<1, 256>>>();

    // routed swiglu: needs eX (for g_xh), eW, and scanplace (stream order)
    cudaStreamWaitEvent(0, eX, 0);
    cudaStreamWaitEvent(0, eW, 0);
    {
        dim3 grid(NTOK / 128, IDIM / 64, NEXP);
        k_swiglu_t<true><<<grid, 256, SMEM_SW>>>();
    }

    // down: needs routed swiglu (stream order) + shared swiglu + down weights
    cudaStreamWaitEvent(0, eSW, 0);
    cudaStreamWaitEvent(0, eB, 0);
    {
        dim3 grid(NTOK / 128, HDIM / 128, NEXP + 1);
        k_down_f<<<grid, 256, SMEM_DN>>>(out);
    }
    // out += partial[n,0] + partial[n,1]
    k_combine<<<(NTOK * HDIM / 4 + 255) / 256, 256>>>(out);

    cudaStreamDestroy(sX);
    cudaStreamDestroy(sW);
    cudaStreamDestroy(sB);
    cudaStreamDestroy(sS);
    cudaEventDestroy(eFork);
    cudaEventDestroy(eX);
    cudaEventDestroy(eW);
    cudaEventDestroy(eB);
    cudaEventDestroy(eSW);
}

// round 16
// speedup vs baseline: 1.6116x; 1.0340x over previous
#include <cuda_runtime.h>
#include <cuda_fp16.h>
#include <math.h>
#include <stdint.h>

// Problem constants
#define NTOK 2048
#define HDIM 2048
#define IDIM 1408
#define NEXP 8
#define ISH  2816
#define TOPK 2
#define CAP  5120

// ----------------------------- scratch --------------------------------------
__device__ int   g_cnt[NEXP];
__device__ int   g_cnt2[NEXP];
__device__ int   g_off[NEXP];
__device__ int   g_rows_token[CAP];
__device__ int   g_rows_slot[CAP];
__device__ float g_rows_w[CAP];
__device__ int   g_tki[NTOK * TOPK];
__device__ float g_tkw[NTOK * TOPK];
__device__ __half g_hbuf[(size_t)CAP * IDIM];
__device__ __half g_sbuf[(size_t)NTOK * ISH];
__device__ __half g_partial[(size_t)NTOK * TOPK * HDIM];   // fp16 partials

// fp16 copies of inputs (converted per call)
__device__ __half g_xh [(size_t)NTOK * HDIM];
__device__ __half g_wgh[(size_t)NEXP * HDIM * IDIM];
__device__ __half g_wuh[(size_t)NEXP * HDIM * IDIM];
__device__ __half g_wdh[(size_t)NEXP * IDIM * HDIM];
__device__ __half g_sgh[(size_t)HDIM * ISH];
__device__ __half g_suh[(size_t)HDIM * ISH];
__device__ __half g_sdh[(size_t)ISH * HDIM];

// ----------------------------- helpers --------------------------------------
__device__ __forceinline__ uint32_t smem_u32(const void* p) {
    uint32_t a;
    asm("{ .reg .u64 t; cvta.to.shared.u64 t, %1; cvt.u32.u64 %0, t; }" : "=r"(a) : "l"(p));
    return a;
}
__device__ __forceinline__ uint32_t pk(float x, float y) {
    __half2 h = __floats2half2_rn(x, y);
    return reinterpret_cast<uint32_t&>(h);
}
#define LDSM4(r0, r1, r2, r3, addr) \
    asm volatile("ldmatrix.sync.aligned.m8n8.x4.shared.b16 {%0,%1,%2,%3}, [%4];" \
        : "=r"(r0), "=r"(r1), "=r"(r2), "=r"(r3) : "r"(addr))
#define LDSM4T(r0, r1, r2, r3, addr) \
    asm volatile("ldmatrix.sync.aligned.m8n8.x4.trans.shared.b16 {%0,%1,%2,%3}, [%4];" \
        : "=r"(r0), "=r"(r1), "=r"(r2), "=r"(r3) : "r"(addr))
#define MMA16(c, a, b0, b1) \
    asm volatile("mma.sync.aligned.m16n8k16.row.col.f32.f16.f16.f32 " \
        "{%0,%1,%2,%3},{%4,%5,%6,%7},{%8,%9},{%0,%1,%2,%3};" \
        : "+f"((c)[0]), "+f"((c)[1]), "+f"((c)[2]), "+f"((c)[3]) \
        : "r"((a)[0]), "r"((a)[1]), "r"((a)[2]), "r"((a)[3]), "r"(b0), "r"(b1))
#define CPA16(dst, src) \
    asm volatile("cp.async.cg.shared.global [%0], [%1], 16;" :: "r"(dst), "l"(src))
#define CPCOMMIT() asm volatile("cp.async.commit_group;" ::: "memory")
#define CPWAIT2()  asm volatile("cp.async.wait_group 2;" ::: "memory")

// SMEM layout (bytes). A: 128 rows x 32 halves, pitch 80. B pitches padded.
#define A_PITCH   80
#define A_BYTES   10240
#define BSW_PITCH 144
#define BSW_BYTES 4608
#define BDN_PITCH 272
#define BDN_BYTES 8704
#define STG_SW    (A_BYTES + 2 * BSW_BYTES)   // 19456
#define STG_DN    (A_BYTES + BDN_BYTES)       // 18944
#define NSTG      4
#define SMEM_SW   (NSTG * STG_SW)             // 77824
#define SMEM_DN   (NSTG * STG_DN)             // 75776

// ----------------------------- fp32 -> fp16 converts -------------------------
__device__ __forceinline__ void cvt_loop(const float4* __restrict__ src,
                                         __half* __restrict__ dst, int n16) {
    int stride = gridDim.x * blockDim.x;
    for (int i = blockIdx.x * blockDim.x + threadIdx.x; i < n16; i += stride) {
        float4 v0 = src[4 * i];
        float4 v1 = src[4 * i + 1];
        float4 v2 = src[4 * i + 2];
        float4 v3 = src[4 * i + 3];
        uint4 o0, o1;
        o0.x = pk(v0.x, v0.y); o0.y = pk(v0.z, v0.w);
        o0.z = pk(v1.x, v1.y); o0.w = pk(v1.z, v1.w);
        o1.x = pk(v2.x, v2.y); o1.y = pk(v2.z, v2.w);
        o1.z = pk(v3.x, v3.y); o1.w = pk(v3.z, v3.w);
        *(uint4*)(dst + (size_t)i * 16) = o0;
        *(uint4*)(dst + (size_t)i * 16 + 8) = o1;
    }
}
// shared-swiglu inputs: z = 0..2 -> x, sw_gate, sw_up
__global__ void __launch_bounds__(256) k_cvtX(
    const float4* __restrict__ x,
    const float4* __restrict__ sg, const float4* __restrict__ su) {
    int z = blockIdx.z;
    const float4* src = z == 0 ? x : z == 1 ? sg : su;
    __half* dst = z == 0 ? g_xh : z == 1 ? g_sgh : g_suh;
    int n16 = z == 0 ? NTOK * HDIM / 16 : HDIM * ISH / 16;
    cvt_loop(src, dst, n16);
}
// routed-swiglu weights: z = 0..1 -> w_gate, w_up
__global__ void __launch_bounds__(256) k_cvtW(
    const float4* __restrict__ wg, const float4* __restrict__ wu) {
    constexpr int n16 = NEXP * HDIM * IDIM / 16;
    int z = blockIdx.z;
    cvt_loop(z == 0 ? wg : wu, z == 0 ? g_wgh : g_wuh, n16);
}
// shared down weight
__global__ void __launch_bounds__(256) k_cvtSd(const float4* __restrict__ sd) {
    cvt_loop(sd, g_sdh, ISH * HDIM / 16);
}
// routed down weights
__global__ void __launch_bounds__(256) k_cvtWd(const float4* __restrict__ wd) {
    cvt_loop(wd, g_wdh, NEXP * IDIM * HDIM / 16);
}

// ----------------------------- small kernels ---------------------------------
__global__ void k_reset() {
    int i = blockIdx.x * blockDim.x + threadIdx.x;
    if (i < NEXP) { g_cnt[i] = 0; g_cnt2[i] = 0; }
    if (i < CAP)  { g_rows_token[i] = 0; g_rows_slot[i] = -1; g_rows_w[i] = 0.f; }
}

__global__ void k_gate(const float* __restrict__ x, const float* __restrict__ gw) {
    int n = blockIdx.x;
    int tid = threadIdx.x;
    const float* xr = x + (size_t)n * HDIM;
    float acc[NEXP];
#pragma unroll
    for (int e = 0; e < NEXP; e++) acc[e] = 0.f;
    for (int h = tid; h < HDIM; h += 128) {
        float xv = xr[h];
#pragma unroll
        for (int e = 0; e < NEXP; e++) acc[e] += xv * gw[e * HDIM + h];
    }
    __shared__ float s[NEXP][128];
#pragma unroll
    for (int e = 0; e < NEXP; e++) s[e][tid] = acc[e];
    __syncthreads();
    for (int st = 64; st > 0; st >>= 1) {
        if (tid < st) {
#pragma unroll
            for (int e = 0; e < NEXP; e++) s[e][tid] += s[e][tid + st];
        }
        __syncthreads();
    }
    if (tid == 0) {
        float l[NEXP];
        float m = -1e30f;
#pragma unroll
        for (int e = 0; e < NEXP; e++) { l[e] = s[e][0]; m = fmaxf(m, l[e]); }
        float d = 0.f;
#pragma unroll
        for (int e = 0; e < NEXP; e++) d += expf(l[e] - m);
        int i1 = 0;
#pragma unroll
        for (int e = 1; e < NEXP; e++) if (l[e] > l[i1]) i1 = e;
        int i2 = -1;
#pragma unroll
        for (int e = 0; e < NEXP; e++) {
            if (e == i1) continue;
            if (i2 < 0 || l[e] > l[i2]) i2 = e;
        }
        g_tki[n * 2 + 0] = i1; g_tkw[n * 2 + 0] = expf(l[i1] - m) / d;
        g_tki[n * 2 + 1] = i2; g_tkw[n * 2 + 1] = expf(l[i2] - m) / d;
        atomicAdd(&g_cnt[i1], 1);
        atomicAdd(&g_cnt[i2], 1);
    }
}

__global__ void k_scanplace() {
    int tid = threadIdx.x;
    if (tid == 0) {
        int o = 0;
        for (int e = 0; e < NEXP; e++) {
            g_off[e] = o;
            o += ((g_cnt[e] + 127) / 128) * 128;
        }
    }
    __syncthreads();
    for (int i = tid; i < NTOK * TOPK; i += blockDim.x) {
        int e = g_tki[i];
        int p = g_off[e] + atomicAdd(&g_cnt2[e], 1);
        g_rows_token[p] = i >> 1;
        g_rows_slot[p]  = i;
        g_rows_w[p]     = g_tkw[i];
    }
}

// ----------------------------- SwiGLU fp16 mma GEMM --------------------------
// ROUTED: grid (16, IDIM/64, NEXP) -> g_hbuf. !ROUTED: grid (16, ISH/64, 1) -> g_sbuf.
// CTA 128M x 64N vs two B matrices. 4-stage cp.async pipeline, k-chunk 32.
template<bool ROUTED>
__global__ void __launch_bounds__(256, 2) k_swiglu_t()
{
    constexpr int K = HDIM;
    constexpr int ncols = ROUTED ? IDIM : ISH;
    const int z = ROUTED ? blockIdx.z : 0;
    int cnt, rowbase;
    const __half *B1, *B2;
    __half* C;
    if (ROUTED) {
        cnt = g_cnt[z]; rowbase = g_off[z];
        B1 = g_wgh + (size_t)z * K * IDIM;
        B2 = g_wuh + (size_t)z * K * IDIM;
        C = g_hbuf;
    } else {
        cnt = NTOK; rowbase = 0;
        B1 = g_sgh; B2 = g_suh; C = g_sbuf;
    }
    const int m0 = blockIdx.x * 128;
    if (m0 >= cnt) return;
    const int n0 = blockIdx.y * 64;

    extern __shared__ __align__(16) char sm[];
    const uint32_t sbase = smem_u32(sm);

    const int tid = threadIdx.x;
    const int lane = tid & 31, wid = tid >> 5;
    const int gid = lane >> 2, tig = lane & 3;
    const int wm = wid >> 2, wn = wid & 3;

    // ---- cp.async slots: A = 2 segs/thread, B = 1 seg/thread/matrix ----
    const __half* aseg[2];
    uint32_t aoff[2];
#pragma unroll
    for (int i = 0; i < 2; i++) {
        int idx = i * 256 + tid;
        int m = idx >> 2, q = idx & 3;
        aoff[i] = (uint32_t)(m * A_PITCH + q * 16);
        int tok;
        if (ROUTED) { int gr = m0 + m; tok = (gr < cnt) ? g_rows_token[rowbase + gr] : 0; }
        else tok = m0 + m;
        aseg[i] = g_xh + (size_t)tok * K + q * 8;
    }
    const int bkk = tid >> 3, bslot = tid & 7;
    const uint32_t boff = (uint32_t)(bkk * BSW_PITCH + bslot * 16);
    const __half* b1s = B1 + (size_t)bkk * ncols + n0 + bslot * 8;
    const __half* b2s = B2 + (size_t)bkk * ncols + n0 + bslot * 8;

    float cg[4][2][4], cu[4][2][4];
#pragma unroll
    for (int mt = 0; mt < 4; mt++)
#pragma unroll
        for (int j = 0; j < 2; j++)
#pragma unroll
            for (int c = 0; c < 4; c++) { cg[mt][j][c] = 0.f; cu[mt][j][c] = 0.f; }

    const uint32_t a_l = (uint32_t)((wm * 64 + (lane & 15)) * A_PITCH + (lane >> 4) * 16);
    const uint32_t b_l4 = (uint32_t)((lane & 15) * BSW_PITCH + (lane >> 4) * 16);

    auto ISSUE = [&](int ch, int buf) {
        uint32_t s0 = sbase + buf * STG_SW;
        size_t k0 = (size_t)ch * 32;
        CPA16(s0 + aoff[0], aseg[0] + k0);
        CPA16(s0 + aoff[1], aseg[1] + k0);
        CPA16(s0 + A_BYTES + boff, b1s + k0 * ncols);
        CPA16(s0 + A_BYTES + BSW_BYTES + boff, b2s + k0 * ncols);
    };
    auto COMPUTE = [&](int buf) {
        uint32_t base = sbase + buf * STG_SW;
#pragma unroll
        for (int s = 0; s < 2; s++) {
            uint32_t a[4][4];
#pragma unroll
            for (int mt = 0; mt < 4; mt++)
                LDSM4(a[mt][0], a[mt][1], a[mt][2], a[mt][3],
                      base + a_l + mt * (16 * A_PITCH) + s * 32);
            uint32_t g[4], u[4];
            uint32_t baddr = base + A_BYTES + b_l4 + s * (16 * BSW_PITCH) + wn * 32;
            LDSM4T(g[0], g[1], g[2], g[3], baddr);
            LDSM4T(u[0], u[1], u[2], u[3], baddr + BSW_BYTES);
#pragma unroll
            for (int mt = 0; mt < 4; mt++) {
                MMA16(cg[mt][0], a[mt], g[0], g[1]);
                MMA16(cu[mt][0], a[mt], u[0], u[1]);
                MMA16(cg[mt][1], a[mt], g[2], g[3]);
                MMA16(cu[mt][1], a[mt], u[2], u[3]);
            }
        }
    };

    constexpr int NC = K / 32;
#pragma unroll
    for (int s = 0; s < NSTG - 1; s++) { ISSUE(s, s); CPCOMMIT(); }
    for (int ch = 0; ch < NC; ch++) {
        CPWAIT2();
        __syncthreads();
        int nx = ch + NSTG - 1;
        if (nx < NC) ISSUE(nx, nx % NSTG);
        CPCOMMIT();
        COMPUTE(ch % NSTG);
    }

    // ---- epilogue: silu(gate)*up -> fp16 ----
#pragma unroll
    for (int mt = 0; mt < 4; mt++) {
        int r0 = m0 + wm * 64 + mt * 16 + gid;
        size_t row0 = (size_t)(rowbase + r0);
        size_t row1 = row0 + 8;
#pragma unroll
        for (int j = 0; j < 2; j++) {
            int col = n0 + wn * 16 + j * 8 + 2 * tig;
            float g0 = cg[mt][j][0], g1 = cg[mt][j][1], g2 = cg[mt][j][2], g3 = cg[mt][j][3];
            float o0 = g0 / (1.f + expf(-g0)) * cu[mt][j][0];
            float o1 = g1 / (1.f + expf(-g1)) * cu[mt][j][1];
            float o2 = g2 / (1.f + expf(-g2)) * cu[mt][j][2];
            float o3 = g3 / (1.f + expf(-g3)) * cu[mt][j][3];
            *(uint32_t*)(C + row0 * ncols + col) = pk(o0, o1);
            *(uint32_t*)(C + row1 * ncols + col) = pk(o2, o3);
        }
    }
}

// ----------------------------- down-proj fp16 mma GEMM -----------------------
// ROUTED: grid (16, 16, NEXP) -> g_partial (fp16, weighted scatter).
// !ROUTED: grid (16, 16, 1) -> out (plain store; partials added by k_combine).
// CTA 128M x 128N. 4-stage cp.async pipeline, k-chunk 32.
template<bool ROUTED>
__global__ void __launch_bounds__(256, 2) k_down_t(float* __restrict__ out)
{
    constexpr int K = ROUTED ? IDIM : ISH;
    const int z = ROUTED ? blockIdx.z : 0;
    int cnt, rowbase;
    const __half *B, *A;
    if (ROUTED) {
        cnt = g_cnt[z]; rowbase = g_off[z];
        B = g_wdh + (size_t)z * IDIM * HDIM;
        A = g_hbuf;
    } else {
        cnt = NTOK; rowbase = 0;
        B = g_sdh;
        A = g_sbuf;
    }
    const int m0 = blockIdx.x * 128;
    if (m0 >= cnt) return;
    const int n0 = blockIdx.y * 128;

    extern __shared__ __align__(16) char sm[];
    const uint32_t sbase = smem_u32(sm);

    const int tid = threadIdx.x;
    const int lane = tid & 31, wid = tid >> 5;
    const int gid = lane >> 2, tig = lane & 3;
    const int wm = wid >> 2, wn = wid & 3;

    // ---- cp.async slots ----
    const __half* aseg[2];
    uint32_t aoff[2];
#pragma unroll
    for (int i = 0; i < 2; i++) {
        int idx = i * 256 + tid;
        int m = idx >> 2, q = idx & 3;
        aoff[i] = (uint32_t)(m * A_PITCH + q * 16);
        aseg[i] = A + (size_t)(rowbase + m0 + m) * K + q * 8;
    }
    const __half* bseg[2];
    uint32_t boff[2];
#pragma unroll
    for (int i = 0; i < 2; i++) {
        int idx = i * 256 + tid;
        int kk = idx >> 4, slot = idx & 15;
        boff[i] = (uint32_t)(kk * BDN_PITCH + slot * 16);
        bseg[i] = B + (size_t)kk * HDIM + n0 + slot * 8;
    }

    float cc[4][4][4];
#pragma unroll
    for (int mt = 0; mt < 4; mt++)
#pragma unroll
        for (int j = 0; j < 4; j++)
#pragma unroll
            for (int c = 0; c < 4; c++) cc[mt][j][c] = 0.f;

    const uint32_t a_l = (uint32_t)((wm * 64 + (lane & 15)) * A_PITCH + (lane >> 4) * 16);
    const uint32_t b_l4 = (uint32_t)((lane & 15) * BDN_PITCH + (lane >> 4) * 16);

    auto ISSUE = [&](int ch, int buf) {
        uint32_t s0 = sbase + buf * STG_DN;
        size_t k0 = (size_t)ch * 32;
        CPA16(s0 + aoff[0], aseg[0] + k0);
        CPA16(s0 + aoff[1], aseg[1] + k0);
        CPA16(s0 + A_BYTES + boff[0], bseg[0] + k0 * HDIM);
        CPA16(s0 + A_BYTES + boff[1], bseg[1] + k0 * HDIM);
    };
    auto COMPUTE = [&](int buf) {
        uint32_t base = sbase + buf * STG_DN;
#pragma unroll
        for (int s = 0; s < 2; s++) {
            uint32_t a[4][4];
#pragma unroll
            for (int mt = 0; mt < 4; mt++)
                LDSM4(a[mt][0], a[mt][1], a[mt][2], a[mt][3],
                      base + a_l + mt * (16 * A_PITCH) + s * 32);
#pragma unroll
            for (int t = 0; t < 2; t++) {
                uint32_t b[4];
                LDSM4T(b[0], b[1], b[2], b[3],
                       base + A_BYTES + b_l4 + s * (16 * BDN_PITCH) + wn * 64 + t * 32);
#pragma unroll
                for (int mt = 0; mt < 4; mt++) {
                    MMA16(cc[mt][t * 2 + 0], a[mt], b[0], b[1]);
                    MMA16(cc[mt][t * 2 + 1], a[mt], b[2], b[3]);
                }
            }
        }
    };

    constexpr int NC = K / 32;
#pragma unroll
    for (int s = 0; s < NSTG - 1; s++) { ISSUE(s, s); CPCOMMIT(); }
    for (int ch = 0; ch < NC; ch++) {
        CPWAIT2();
        __syncthreads();
        int nx = ch + NSTG - 1;
        if (nx < NC) ISSUE(nx, nx % NSTG);
        CPCOMMIT();
        COMPUTE(ch % NSTG);
    }

    // ---- epilogue ----
#pragma unroll
    for (int mt = 0; mt < 4; mt++) {
        int r0 = m0 + wm * 64 + mt * 16 + gid;
        if (ROUTED) {
            int gr0 = rowbase + r0, gr1 = gr0 + 8;
            int s0 = g_rows_slot[gr0], s1 = g_rows_slot[gr1];
            float w0 = g_rows_w[gr0],  w1 = g_rows_w[gr1];
#pragma unroll
            for (int j = 0; j < 4; j++) {
                int col = n0 + wn * 32 + j * 8 + 2 * tig;
                if (s0 >= 0)
                    *(uint32_t*)(g_partial + (size_t)s0 * HDIM + col) =
                        pk(w0 * cc[mt][j][0], w0 * cc[mt][j][1]);
                if (s1 >= 0)
                    *(uint32_t*)(g_partial + (size_t)s1 * HDIM + col) =
                        pk(w1 * cc[mt][j][2], w1 * cc[mt][j][3]);
            }
        } else {
            int r1 = r0 + 8;
#pragma unroll
            for (int j = 0; j < 4; j++) {
                int col = n0 + wn * 32 + j * 8 + 2 * tig;
                *(float2*)(out + (size_t)r0 * HDIM + col) =
                    make_float2(cc[mt][j][0], cc[mt][j][1]);
                *(float2*)(out + (size_t)r1 * HDIM + col) =
                    make_float2(cc[mt][j][2], cc[mt][j][3]);
            }
        }
    }
}

// ----------------------------- final combine ---------------------------------
__global__ void __launch_bounds__(256) k_combine(float* __restrict__ out) {
    size_t base = ((size_t)blockIdx.x * blockDim.x + threadIdx.x) * 4;
    if (base >= (size_t)NTOK * HDIM) return;
    int n = (int)(base >> 11);          // HDIM = 2048
    int h = (int)(base & 2047);
    float4 o = *(float4*)(out + base);
    const __half2* p0 = (const __half2*)(g_partial + (size_t)(2 * n) * HDIM + h);
    const __half2* p1 = (const __half2*)(g_partial + (size_t)(2 * n + 1) * HDIM + h);
    float2 a0 = __half22float2(p0[0]);
    float2 a1 = __half22float2(p0[1]);
    float2 b0 = __half22float2(p1[0]);
    float2 b1 = __half22float2(p1[1]);
    o.x += a0.x + b0.x;
    o.y += a0.y + b0.y;
    o.z += a1.x + b1.x;
    o.w += a1.y + b1.y;
    *(float4*)(out + base) = o;
}

// ----------------------------- launch ----------------------------------------
extern "C" void kernel_launch(void* const* d_in, const int* in_sizes, int n_in,
                              void* d_out, int out_size)
{
    const float* x       = (const float*)d_in[0];
    const float* gate_w  = (const float*)d_in[1];
    const float* w_gate  = (const float*)d_in[2];
    const float* w_up    = (const float*)d_in[3];
    const float* w_down  = (const float*)d_in[4];
    const float* sw_gate = (const float*)d_in[5];
    const float* sw_up   = (const float*)d_in[6];
    const float* sw_down = (const float*)d_in[7];
    float* out = (float*)d_out;

    cudaFuncSetAttribute(k_swiglu_t<true>,
                         cudaFuncAttributeMaxDynamicSharedMemorySize, SMEM_SW);
    cudaFuncSetAttribute(k_swiglu_t<false>,
                         cudaFuncAttributeMaxDynamicSharedMemorySize, SMEM_SW);
    cudaFuncSetAttribute(k_down_t<true>,
                         cudaFuncAttributeMaxDynamicSharedMemorySize, SMEM_DN);
    cudaFuncSetAttribute(k_down_t<false>,
                         cudaFuncAttributeMaxDynamicSharedMemorySize, SMEM_DN);

    // DAG: split downs remove false cross-dependencies; shared-down overlaps
    // routed swiglu. 4 streams / 6 events (both counts proven guard-safe).
    //   sX: cvt(x, sw_gate, sw_up) ──eX
    //   sW: cvt(w_gate, w_up) ──eW
    //   sB: cvt(sw_down) ──eBs── cvt(w_down) ──eB
    //   sS: (wait eX) shared swiglu ─(wait eBs)─ shared down ──eS
    //   main: reset,gate,scan ─(wait eX,eW)─ routed swiglu
    //         ─(wait eB)─ routed down ─(wait eS)─ combine
    int prLo, prHi;
    cudaDeviceGetStreamPriorityRange(&prLo, &prHi);
    cudaStream_t sX, sW, sB, sS;
    cudaEvent_t eFork, eX, eW, eBs, eB, eS;
    cudaStreamCreateWithPriority(&sX, cudaStreamNonBlocking, prHi);
    cudaStreamCreateWithPriority(&sW, cudaStreamNonBlocking, prHi);
    cudaStreamCreateWithFlags(&sB, cudaStreamNonBlocking);
    cudaStreamCreateWithFlags(&sS, cudaStreamNonBlocking);
    cudaEventCreateWithFlags(&eFork, cudaEventDisableTiming);
    cudaEventCreateWithFlags(&eX, cudaEventDisableTiming);
    cudaEventCreateWithFlags(&eW, cudaEventDisableTiming);
    cudaEventCreateWithFlags(&eBs, cudaEventDisableTiming);
    cudaEventCreateWithFlags(&eB, cudaEventDisableTiming);
    cudaEventCreateWithFlags(&eS, cudaEventDisableTiming);

    cudaEventRecord(eFork, 0);
    cudaStreamWaitEvent(sX, eFork, 0);
    cudaStreamWaitEvent(sW, eFork, 0);
    cudaStreamWaitEvent(sB, eFork, 0);

    // small converts feeding the shared swiglu
    k_cvtX<<<dim3(240, 1, 3), 256, 0, sX>>>(
        (const float4*)x, (const float4*)sw_gate, (const float4*)sw_up);
    cudaEventRecord(eX, sX);

    // big routed-weight converts (overlap the shared swiglu)
    k_cvtW<<<dim3(432, 1, 2), 256, 0, sW>>>(
        (const float4*)w_gate, (const float4*)w_up);
    cudaEventRecord(eW, sW);

    // down-side converts: shared first (early event), then routed
    k_cvtSd<<<dim3(240, 1, 1), 256, 0, sB>>>((const float4*)sw_down);
    cudaEventRecord(eBs, sB);
    k_cvtWd<<<dim3(432, 1, 1), 256, 0, sB>>>((const float4*)w_down);
    cudaEventRecord(eB, sB);

    // shared chain: swiglu -> down (down overlaps routed swiglu on main)
    cudaStreamWaitEvent(sS, eX, 0);
    {
        dim3 grid(NTOK / 128, ISH / 64, 1);
        k_swiglu_t<false><<<grid, 256, SMEM_SW, sS>>>();
    }
    cudaStreamWaitEvent(sS, eBs, 0);
    {
        dim3 grid(NTOK / 128, HDIM / 128, 1);
        k_down_t<false><<<grid, 256, SMEM_DN, sS>>>(out);
    }
    cudaEventRecord(eS, sS);

    // main: routing chain (concurrent with all converts)
    k_reset<<<(CAP + 255) / 256, 256>>>();
    k_gate<<<NTOK, 128>>>(x, gate_w);
    k_scanplace<<<1, 256>>>();

    // routed swiglu: needs eX (for g_xh), eW, and scanplace (stream order)
    cudaStreamWaitEvent(0, eX, 0);
    cudaStreamWaitEvent(0, eW, 0);
    {
        dim3 grid(NTOK / 128, IDIM / 64, NEXP);
        k_swiglu_t<true><<<grid, 256, SMEM_SW>>>();
    }

    // routed down: needs routed swiglu (stream order) + w_down weights
    cudaStreamWaitEvent(0, eB, 0);
    {
        dim3 grid(NTOK / 128, HDIM / 128, NEXP);
        k_down_t<true><<<grid, 256, SMEM_DN>>>(out);
    }
    // combine after shared chain too
    cudaStreamWaitEvent(0, eS, 0);
    k_combine<<<(NTOK * HDIM / 4 + 255) / 256, 256>>>(out);

    cudaStreamDestroy(sX);
    cudaStreamDestroy(sW);
    cudaStreamDestroy(sB);
    cudaStreamDestroy(sS);
    cudaEventDestroy(eFork);
    cudaEventDestroy(eX);
    cudaEventDestroy(eW);
    cudaEventDestroy(eBs);
    cudaEventDestroy(eB);
    cudaEventDestroy(eS);
}